// round 14
// baseline (speedup 1.0000x reference)
#include <cuda_runtime.h>
#include <cuda_bf16.h>
#include <cstdint>
#include <cstddef>

#define BB 8
#define TT 2048
#define CC 1024
#define HH 64

// ---------------------------------------------------------------------------
// Scratch (device globals; no allocations allowed)
// ---------------------------------------------------------------------------
__device__ __nv_bfloat16 g_Whi[3 * HH * CC];     // [Wq;Wk;Wv] stacked, hi
__device__ __nv_bfloat16 g_Wlo[3 * HH * CC];     // lo
__device__ __nv_bfloat16 g_Qhi[BB * TT * HH];    // Q * log2(e), hi/lo
__device__ __nv_bfloat16 g_Qlo[BB * TT * HH];
__device__ __nv_bfloat16 g_Khi[BB * TT * HH];
__device__ __nv_bfloat16 g_Klo[BB * TT * HH];
__device__ __nv_bfloat16 g_Vhi[BB * TT * HH];    // V [s][h] hi/lo (unscaled)
__device__ __nv_bfloat16 g_Vlo[BB * TT * HH];
__device__ __nv_bfloat16 g_Vphi[BB * TT * HH];   // V' = V*rD [s][h] hi/lo
__device__ __nv_bfloat16 g_Vplo[BB * TT * HH];
// P = exp2(S) stored as mma A-fragments:
// index = ((((b*32 + ti)*32 + si)*16 + rb*4 + kb)*32 + lane), uint4 per lane
__device__ uint4         g_Pfh[(size_t)BB * 32 * 32 * 16 * 32];  // 64MB
__device__ uint4         g_Pfl[(size_t)BB * 32 * 32 * 16 * 32];  // 64MB
__device__ float         g_Dp[BB][4][TT];        // colsum partials
__device__ float         g_O4[4][BB * TT * HH];  // 4-way split-s partial outputs

// ---------------------------------------------------------------------------
// Helpers (plain sm_80+ PTX, no 'a' features)
// ---------------------------------------------------------------------------
__device__ __forceinline__ uint32_t smem_u32(const void* p) {
    uint32_t r;
    asm("{ .reg .u64 t; cvta.to.shared.u64 t, %1; cvt.u32.u64 %0, t; }"
        : "=r"(r) : "l"(p));
    return r;
}
__device__ __forceinline__ uint32_t swz(uint32_t o) { return o ^ ((o >> 3) & 0x70); }

__device__ __forceinline__ void ldsm4(uint32_t (&r)[4], uint32_t addr) {
    asm volatile("ldmatrix.sync.aligned.m8n8.x4.shared.b16 {%0,%1,%2,%3}, [%4];"
                 : "=r"(r[0]), "=r"(r[1]), "=r"(r[2]), "=r"(r[3]) : "r"(addr));
}
__device__ __forceinline__ void ldsm4t(uint32_t (&r)[4], uint32_t addr) {
    asm volatile("ldmatrix.sync.aligned.m8n8.x4.trans.shared.b16 {%0,%1,%2,%3}, [%4];"
                 : "=r"(r[0]), "=r"(r[1]), "=r"(r[2]), "=r"(r[3]) : "r"(addr));
}
__device__ __forceinline__ void mma2(float (&c)[4], const uint32_t (&a)[4],
                                     uint32_t b0, uint32_t b1) {
    asm volatile(
        "mma.sync.aligned.m16n8k16.row.col.f32.bf16.bf16.f32 "
        "{%0,%1,%2,%3}, {%4,%5,%6,%7}, {%8,%9}, {%0,%1,%2,%3};"
        : "+f"(c[0]), "+f"(c[1]), "+f"(c[2]), "+f"(c[3])
        : "r"(a[0]), "r"(a[1]), "r"(a[2]), "r"(a[3]), "r"(b0), "r"(b1));
}
__device__ __forceinline__ float ex2(float x) {
    float y;
    asm("ex2.approx.f32 %0, %1;" : "=f"(y) : "f"(x));
    return y;
}
__device__ __forceinline__ void cp16(uint32_t dst, const void* src) {
    asm volatile("cp.async.cg.shared.global [%0], [%1], 16;"
                 :: "r"(dst), "l"(src));
}
#define CP_COMMIT() asm volatile("cp.async.commit_group;" ::: "memory")
#define CP_WAIT1()  asm volatile("cp.async.wait_group 1;" ::: "memory")

// A-fragment: 16x16 bf16, row-major tile rows = mr.., k-bytes = kb..kb+31
__device__ __forceinline__ void lda(uint32_t (&a)[4], uint32_t base, int mr,
                                    int kb, int lane) {
    ldsm4(a, base + swz(((mr + (lane & 15)) << 7) + kb + ((lane >> 4) << 4)));
}
// B-fragments for TWO n8 tiles (n16 x k16) from [n][k] row-major tile
__device__ __forceinline__ void ldb4(uint32_t (&b)[4], uint32_t base, int nr,
                                     int kb, int lane) {
    int row = nr + (lane & 7) + ((lane >> 4) << 3);
    int kx  = kb + (((lane >> 3) & 1) << 4);
    ldsm4(b, base + swz((row << 7) + kx));
}
// B-fragments for TWO n8 tiles from a [k][n] row-major tile via trans ldmatrix
__device__ __forceinline__ void ldb4t(uint32_t (&b)[4], uint32_t base, int nr,
                                      int ksel, int lane) {
    int row  = ksel + (lane & 7) + (((lane >> 3) & 1) << 3);
    int colb = nr * 2 + ((lane >> 4) << 4);
    ldsm4t(b, base + swz((row << 7) + colb));
}

__device__ __forceinline__ void split_bf16(float x, __nv_bfloat16& h, __nv_bfloat16& l) {
    h = __float2bfloat16(x);
    l = __float2bfloat16(x - __bfloat162float(h));
}
// Fast pair split: hi = packed bf16(x,y); lo = packed bf16 of residuals.
__device__ __forceinline__ void splitpack2(float x, float y, uint32_t& hi, uint32_t& lo) {
    uint32_t H;
    asm("cvt.rn.bf16x2.f32 %0, %1, %2;" : "=r"(H) : "f"(y), "f"(x));
    float fx = __uint_as_float(H << 16);
    float fy = __uint_as_float(H & 0xFFFF0000u);
    uint32_t L;
    asm("cvt.rn.bf16x2.f32 %0, %1, %2;" : "=r"(L) : "f"(y - fy), "f"(x - fx));
    hi = H; lo = L;
}

// ---------------------------------------------------------------------------
// K0: split weights once into stacked [192][1024] hi/lo (Q,K,V order)
// ---------------------------------------------------------------------------
__global__ void __launch_bounds__(256) prep_w(
    const float* __restrict__ Wk,
    const float* __restrict__ Wq,
    const float* __restrict__ Wv)
{
    int i = blockIdx.x * 256 + threadIdx.x;          // < 196608
    int w = i >> 16;
    int rem = i & 65535;
    const float* src = (w == 0) ? Wq : (w == 1) ? Wk : Wv;
    __nv_bfloat16 h, l;
    split_bf16(src[rem], h, l);
    g_Whi[i] = h; g_Wlo[i] = l;
}

// ---------------------------------------------------------------------------
// K1: QKV projection, fused + pipelined. Grid 256 CTAs, 256 threads.
// A chunk prefetched in registers; W chunks cp.async double-buffered.
// smem: Ah(8K) Al(8K) Wst0(48K) Wst1(48K) = 114688
// ---------------------------------------------------------------------------
__global__ void __launch_bounds__(256) proj_mma(const float* __restrict__ A)
{
    extern __shared__ char smem[];
    char* Ah = smem;
    char* Al = smem + 8192;
    const uint32_t sb = smem_u32(smem);
    const uint32_t sAh = sb, sAl = sb + 8192;

    const int tid = threadIdx.x, wid = tid >> 5, lane = tid & 31;
    const int wm = wid >> 2, wn = wid & 3;
    const int gid = lane >> 2, tig = lane & 3;
    const int m0 = blockIdx.x * 64;

    auto issueW = [&](int ch, int st) {
        const int c0 = ch * 64;
        uint32_t base = sb + 16384 + st * 49152;
#pragma unroll
        for (int i = 0; i < 6; ++i) {
            int u = i * 256 + tid, r = u >> 3, q = u & 7;
            uint32_t off = swz(r * 128 + q * 16);
            cp16(base + off,         g_Whi + (size_t)r * CC + c0 + q * 8);
            cp16(base + 24576 + off, g_Wlo + (size_t)r * CC + c0 + q * 8);
        }
    };

    float2 aReg[8];
    auto loadA = [&](int ch) {
        const int c0 = ch * 64;
#pragma unroll
        for (int i = 0; i < 8; ++i) {
            int p = i * 256 + tid, r = p >> 5, cp = p & 31;
            aReg[i] = *(const float2*)&A[(size_t)(m0 + r) * CC + c0 + cp * 2];
        }
    };

    float acc[2][6][4];
#pragma unroll
    for (int i = 0; i < 2; ++i)
#pragma unroll
        for (int j = 0; j < 6; ++j)
#pragma unroll
            for (int k = 0; k < 4; ++k) acc[i][j][k] = 0.f;

    loadA(0);
    issueW(0, 0);
    CP_COMMIT();

    for (int ch = 0; ch < 16; ++ch) {
        // split current A chunk from registers into smem
#pragma unroll
        for (int i = 0; i < 8; ++i) {
            int p = i * 256 + tid, r = p >> 5, cp = p & 31;
            uint32_t hi, lo; splitpack2(aReg[i].x, aReg[i].y, hi, lo);
            uint32_t off = swz(r * 128 + cp * 4);
            *(uint32_t*)(Ah + off) = hi; *(uint32_t*)(Al + off) = lo;
        }
        if (ch < 15) issueW(ch + 1, (ch + 1) & 1);
        CP_COMMIT();
        CP_WAIT1();
        __syncthreads();
        if (ch < 15) loadA(ch + 1);   // prefetch next A chunk (latency under MMA)

        const uint32_t sWh = sb + 16384 + (ch & 1) * 49152;
        const uint32_t sWl = sWh + 24576;

#pragma unroll
        for (int ks = 0; ks < 4; ++ks) {
            const int kb = ks * 32;
            uint32_t ah0[4], ah1[4], al0[4], al1[4];
            lda(ah0, sAh, wm * 32, kb, lane);      lda(ah1, sAh, wm * 32 + 16, kb, lane);
            lda(al0, sAl, wm * 32, kb, lane);      lda(al1, sAl, wm * 32 + 16, kb, lane);
#pragma unroll
            for (int jp = 0; jp < 3; ++jp) {
                uint32_t bh[4], bl[4];
                ldb4(bh, sWh, wn * 48 + jp * 16, kb, lane);
                ldb4(bl, sWl, wn * 48 + jp * 16, kb, lane);
                mma2(acc[0][2 * jp], ah0, bh[0], bh[1]);
                mma2(acc[0][2 * jp], ah0, bl[0], bl[1]);
                mma2(acc[0][2 * jp], al0, bh[0], bh[1]);
                mma2(acc[1][2 * jp], ah1, bh[0], bh[1]);
                mma2(acc[1][2 * jp], ah1, bl[0], bl[1]);
                mma2(acc[1][2 * jp], al1, bh[0], bh[1]);
                mma2(acc[0][2 * jp + 1], ah0, bh[2], bh[3]);
                mma2(acc[0][2 * jp + 1], ah0, bl[2], bl[3]);
                mma2(acc[0][2 * jp + 1], al0, bh[2], bh[3]);
                mma2(acc[1][2 * jp + 1], ah1, bh[2], bh[3]);
                mma2(acc[1][2 * jp + 1], ah1, bl[2], bl[3]);
                mma2(acc[1][2 * jp + 1], al1, bh[2], bh[3]);
            }
        }
        __syncthreads();
    }

    // epilogue: cols 0-63 Q (x log2e), 64-127 K, 128-191 V — all split hi/lo
#pragma unroll
    for (int mf = 0; mf < 2; ++mf)
#pragma unroll
        for (int j = 0; j < 6; ++j) {
            int base = wn * 48 + j * 8;
            int reg = base >> 6;
            int col = (base & 63) + 2 * tig;
            int m = m0 + wm * 32 + mf * 16 + gid;
            uint32_t* oh = (reg == 0) ? (uint32_t*)g_Qhi
                         : (reg == 1) ? (uint32_t*)g_Khi : (uint32_t*)g_Vhi;
            uint32_t* ol = (reg == 0) ? (uint32_t*)g_Qlo
                         : (reg == 1) ? (uint32_t*)g_Klo : (uint32_t*)g_Vlo;
            float sc = (reg == 0) ? 1.44269504f : 1.f;
            uint32_t hi, lo;
            splitpack2(acc[mf][j][0] * sc, acc[mf][j][1] * sc, hi, lo);
            size_t o = ((size_t)m * HH + col) >> 1;
            oh[o] = hi; ol[o] = lo;
            splitpack2(acc[mf][j][2] * sc, acc[mf][j][3] * sc, hi, lo);
            o = ((size_t)(m + 8) * HH + col) >> 1;
            oh[o] = hi; ol[o] = lo;
        }
}

// ---------------------------------------------------------------------------
// K2 (pass1): S = QK^T once; P = exp2(S) stored as A-FRAGMENTS to gmem;
// colsum D partials. Grid (32 s-tiles, 4 t-chunks, B), 128 threads.
// cp.async double-buffered Q chunks. smem: Kh/Kl(16K) Qst(32K) red(512B)
// ---------------------------------------------------------------------------
__global__ void __launch_bounds__(128, 3) pass1_colsum()
{
    extern __shared__ char smem[];
    char* Kh = smem;                          // 8K
    char* Kl = smem + 8192;                   // 8K
    float* red = (float*)(smem + 49152);      // [2][64]
    const uint32_t sb = smem_u32(smem);
    const uint32_t sKh = sb, sKl = sb + 8192;

    const int tid = threadIdx.x, wid = tid >> 5, lane = tid & 31;
    const int wm = wid >> 1, wn = wid & 1;
    const int gid = lane >> 2, tig = lane & 3;
    const int s0 = blockIdx.x * 64;
    const int ch = blockIdx.y;
    const int b  = blockIdx.z;

    {   // K tile (persistent) 64x64 hi/lo
        const __nv_bfloat16* sh = g_Khi + ((size_t)b * TT + s0) * HH;
        const __nv_bfloat16* sl = g_Klo + ((size_t)b * TT + s0) * HH;
#pragma unroll
        for (int j = 0; j < 4; ++j) {
            int u = j * 128 + tid, r = u >> 3, q = u & 7;
            uint32_t off = swz(r * 128 + q * 16);
            *(uint4*)(Kh + off) = *(const uint4*)(sh + r * HH + q * 8);
            *(uint4*)(Kl + off) = *(const uint4*)(sl + r * HH + q * 8);
        }
    }

    float csum[4][2];
#pragma unroll
    for (int i = 0; i < 4; ++i) { csum[i][0] = 0.f; csum[i][1] = 0.f; }

    const int tbase  = ch * 512;
    const int t_end  = tbase + 512;
    const int t_first = (tbase > s0) ? tbase : s0;

    auto issueQ = [&](int t0, int st) {
        const __nv_bfloat16* sh = g_Qhi + ((size_t)b * TT + t0) * HH;
        const __nv_bfloat16* sl = g_Qlo + ((size_t)b * TT + t0) * HH;
        uint32_t qb = sb + 16384 + st * 16384;
#pragma unroll
        for (int j = 0; j < 4; ++j) {
            int u = j * 128 + tid, r = u >> 3, q = u & 7;
            uint32_t off = swz(r * 128 + q * 16);
            cp16(qb + off,        sh + r * HH + q * 8);
            cp16(qb + 8192 + off, sl + r * HH + q * 8);
        }
    };

    if (t_first < t_end) issueQ(t_first, 0);
    CP_COMMIT();
    int stage = 0;

    for (int t0 = t_first; t0 < t_end; t0 += 64) {
        if (t0 + 64 < t_end) issueQ(t0 + 64, stage ^ 1);
        CP_COMMIT();
        CP_WAIT1();
        __syncthreads();

        const uint32_t sQh = sb + 16384 + stage * 16384;
        const uint32_t sQl = sQh + 8192;

        float acc[2][4][4];
#pragma unroll
        for (int i = 0; i < 2; ++i)
#pragma unroll
            for (int j = 0; j < 4; ++j)
#pragma unroll
                for (int k = 0; k < 4; ++k) acc[i][j][k] = 0.f;

#pragma unroll
        for (int ks = 0; ks < 4; ++ks) {
            const int kb = ks * 32;
            uint32_t ah0[4], ah1[4], al0[4], al1[4];
            lda(ah0, sQh, wm * 32, kb, lane);      lda(ah1, sQh, wm * 32 + 16, kb, lane);
            lda(al0, sQl, wm * 32, kb, lane);      lda(al1, sQl, wm * 32 + 16, kb, lane);
#pragma unroll
            for (int jp = 0; jp < 2; ++jp) {
                uint32_t bh[4], bl[4];
                ldb4(bh, sKh, wn * 32 + jp * 16, kb, lane);
                ldb4(bl, sKl, wn * 32 + jp * 16, kb, lane);
                mma2(acc[0][2 * jp], ah0, bh[0], bh[1]);
                mma2(acc[0][2 * jp], ah0, bl[0], bl[1]);
                mma2(acc[0][2 * jp], al0, bh[0], bh[1]);
                mma2(acc[1][2 * jp], ah1, bh[0], bh[1]);
                mma2(acc[1][2 * jp], ah1, bl[0], bl[1]);
                mma2(acc[1][2 * jp], al1, bh[0], bh[1]);
                mma2(acc[0][2 * jp + 1], ah0, bh[2], bh[3]);
                mma2(acc[0][2 * jp + 1], ah0, bl[2], bl[3]);
                mma2(acc[0][2 * jp + 1], al0, bh[2], bh[3]);
                mma2(acc[1][2 * jp + 1], ah1, bh[2], bh[3]);
                mma2(acc[1][2 * jp + 1], ah1, bl[2], bl[3]);
                mma2(acc[1][2 * jp + 1], al1, bh[2], bh[3]);
            }
        }
        __syncthreads();       // Q stage free for next iteration's cp.async

        // exp2 + (mask only on diagonal tile) -> e; colsums
        float e[2][4][4];
        if (t0 >= s0 + 64) {
#pragma unroll
            for (int mf = 0; mf < 2; ++mf)
#pragma unroll
                for (int nf = 0; nf < 4; ++nf) {
                    e[mf][nf][0] = ex2(acc[mf][nf][0]);
                    e[mf][nf][1] = ex2(acc[mf][nf][1]);
                    e[mf][nf][2] = ex2(acc[mf][nf][2]);
                    e[mf][nf][3] = ex2(acc[mf][nf][3]);
                }
        } else {
#pragma unroll
            for (int mf = 0; mf < 2; ++mf) {
                int r0 = t0 + wm * 32 + mf * 16 + gid;
                int r1 = r0 + 8;
#pragma unroll
                for (int nf = 0; nf < 4; ++nf) {
                    int c = s0 + wn * 32 + nf * 8 + 2 * tig;
                    e[mf][nf][0] = (r0 >= c)     ? ex2(acc[mf][nf][0]) : 0.f;
                    e[mf][nf][1] = (r0 >= c + 1) ? ex2(acc[mf][nf][1]) : 0.f;
                    e[mf][nf][2] = (r1 >= c)     ? ex2(acc[mf][nf][2]) : 0.f;
                    e[mf][nf][3] = (r1 >= c + 1) ? ex2(acc[mf][nf][3]) : 0.f;
                }
            }
        }
#pragma unroll
        for (int mf = 0; mf < 2; ++mf)
#pragma unroll
            for (int nf = 0; nf < 4; ++nf) {
                csum[nf][0] += e[mf][nf][0] + e[mf][nf][2];
                csum[nf][1] += e[mf][nf][1] + e[mf][nf][3];
            }

        // direct A-fragment store of P hi/lo (coalesced STG.128)
        {
            size_t fb = ((((size_t)b * 32 + (t0 >> 6)) * 32 + (s0 >> 6)) * 16) * 32 + lane;
            uint4* ph = g_Pfh + fb;
            uint4* pl = g_Pfl + fb;
#pragma unroll
            for (int mf = 0; mf < 2; ++mf)
#pragma unroll
                for (int jp = 0; jp < 2; ++jp) {
                    int frag = (2 * wm + mf) * 4 + (2 * wn + jp);
                    uint32_t h0, h1, h2, h3, l0, l1, l2, l3;
                    splitpack2(e[mf][2 * jp][0],     e[mf][2 * jp][1],     h0, l0);
                    splitpack2(e[mf][2 * jp][2],     e[mf][2 * jp][3],     h1, l1);
                    splitpack2(e[mf][2 * jp + 1][0], e[mf][2 * jp + 1][1], h2, l2);
                    splitpack2(e[mf][2 * jp + 1][2], e[mf][2 * jp + 1][3], h3, l3);
                    ph[frag * 32] = make_uint4(h0, h1, h2, h3);
                    pl[frag * 32] = make_uint4(l0, l1, l2, l3);
                }
        }
        stage ^= 1;
    }

    __syncthreads();
#pragma unroll
    for (int nf = 0; nf < 4; ++nf)
#pragma unroll
        for (int d = 0; d < 2; ++d) {
            float v = csum[nf][d];
            v += __shfl_xor_sync(0xffffffffu, v, 4);
            v += __shfl_xor_sync(0xffffffffu, v, 8);
            v += __shfl_xor_sync(0xffffffffu, v, 16);
            if (lane < 4)
                red[wm * 64 + wn * 32 + nf * 8 + 2 * lane + d] = v;
        }
    __syncthreads();
    if (tid < 64)
        g_Dp[b][ch][s0 + tid] = red[tid] + red[64 + tid];
}

// ---------------------------------------------------------------------------
// K3: V' = V * rD, split hi/lo (folds the column normalizer into V)
// ---------------------------------------------------------------------------
__global__ void __launch_bounds__(256) vscale()
{
    int p = blockIdx.x * 256 + threadIdx.x;        // pair index < BB*TT*32
    int row = p >> 5;                              // b*TT + s
    int b = row >> 11, s = row & 2047;
    float d = g_Dp[b][0][s] + g_Dp[b][1][s] + g_Dp[b][2][s] + g_Dp[b][3][s];
    float rd = 1.f / d;
    uint32_t H = ((const uint32_t*)g_Vhi)[p];
    uint32_t L = ((const uint32_t*)g_Vlo)[p];
    __nv_bfloat162 h2 = *(__nv_bfloat162*)&H;
    __nv_bfloat162 l2 = *(__nv_bfloat162*)&L;
    float v0 = (__bfloat162float(h2.x) + __bfloat162float(l2.x)) * rd;
    float v1 = (__bfloat162float(h2.y) + __bfloat162float(l2.y)) * rd;
    uint32_t oh, ol; splitpack2(v0, v1, oh, ol);
    ((uint32_t*)g_Vphi)[p] = oh;
    ((uint32_t*)g_Vplo)[p] = ol;
}

// ---------------------------------------------------------------------------
// K4 (pass2): pure GEMM O += P V'. Grid (32 t-tiles, 4 s-splits, B).
// A-fragments of P loaded straight from gmem (LDG.128, no smem / ldmatrix).
// V tiles cp.async double-buffered (16KB x 2). 4 CTAs/SM.
// ---------------------------------------------------------------------------
__global__ void __launch_bounds__(128, 4) pass2_pv()
{
    extern __shared__ char smem[];
    const uint32_t sb = smem_u32(smem);

    const int tid = threadIdx.x, wid = tid >> 5, lane = tid & 31;
    const int wm = wid >> 1, wn = wid & 1;
    const int gid = lane >> 2, tig = lane & 3;
    const int ti = 31 - blockIdx.x;             // heavy tiles first
    const int q4 = blockIdx.y;
    const int b  = blockIdx.z;
    const int t0 = ti * 64;
    const int nS = ti + 1;

    auto issueV = [&](int si, int st) {
        const int s0 = si * 64;
        const __nv_bfloat16* vh = g_Vphi + ((size_t)b * TT + s0) * HH;
        const __nv_bfloat16* vl = g_Vplo + ((size_t)b * TT + s0) * HH;
        uint32_t base = sb + st * 16384;
#pragma unroll
        for (int j = 0; j < 4; ++j) {
            int u = j * 128 + tid, r = u >> 3, q = u & 7;
            uint32_t off = swz(r * 128 + q * 16);
            cp16(base + off,        vh + r * HH + q * 8);
            cp16(base + 8192 + off, vl + r * HH + q * 8);
        }
    };

    float O[2][4][4];
#pragma unroll
    for (int i = 0; i < 2; ++i)
#pragma unroll
        for (int j = 0; j < 4; ++j)
#pragma unroll
            for (int k = 0; k < 4; ++k) O[i][j][k] = 0.f;

    if (q4 < nS) issueV(q4, 0);
    CP_COMMIT();
    int stage = 0;

    for (int si = q4; si < nS; si += 4) {
        if (si + 4 < nS) issueV(si + 4, stage ^ 1);
        CP_COMMIT();
        CP_WAIT1();
        __syncthreads();

        const uint32_t sVh = sb + stage * 16384;
        const uint32_t sVl = sVh + 8192;
        const size_t fb = ((((size_t)b * 32 + ti) * 32 + si) * 16) * 32 + lane;
        const uint4* ph = g_Pfh + fb;
        const uint4* pl = g_Pfl + fb;

#pragma unroll
        for (int ks = 0; ks < 4; ++ks) {
            uint32_t ah0[4], ah1[4], al0[4], al1[4];
            *(uint4*)ah0 = ph[((2 * wm)     * 4 + ks) * 32];
            *(uint4*)ah1 = ph[((2 * wm + 1) * 4 + ks) * 32];
            *(uint4*)al0 = pl[((2 * wm)     * 4 + ks) * 32];
            *(uint4*)al1 = pl[((2 * wm + 1) * 4 + ks) * 32];
#pragma unroll
            for (int jp = 0; jp < 2; ++jp) {
                uint32_t bh[4], bl[4];
                ldb4t(bh, sVh, wn * 32 + jp * 16, ks * 16, lane);
                ldb4t(bl, sVl, wn * 32 + jp * 16, ks * 16, lane);
                mma2(O[0][2 * jp], ah0, bh[0], bh[1]);
                mma2(O[0][2 * jp], ah0, bl[0], bl[1]);
                mma2(O[0][2 * jp], al0, bh[0], bh[1]);
                mma2(O[1][2 * jp], ah1, bh[0], bh[1]);
                mma2(O[1][2 * jp], ah1, bl[0], bl[1]);
                mma2(O[1][2 * jp], al1, bh[0], bh[1]);
                mma2(O[0][2 * jp + 1], ah0, bh[2], bh[3]);
                mma2(O[0][2 * jp + 1], ah0, bl[2], bl[3]);
                mma2(O[0][2 * jp + 1], al0, bh[2], bh[3]);
                mma2(O[1][2 * jp + 1], ah1, bh[2], bh[3]);
                mma2(O[1][2 * jp + 1], ah1, bl[2], bl[3]);
                mma2(O[1][2 * jp + 1], al1, bh[2], bh[3]);
            }
        }
        __syncthreads();      // V stage free for next iteration's cp.async
        stage ^= 1;
    }

    // epilogue: each warp owns rows (wm*32..+31) x cols (wn*32..+31)
    float* Ob = g_O4[q4] + ((size_t)b * TT + t0) * HH;
    if (q4 < nS) {
#pragma unroll
        for (int mf = 0; mf < 2; ++mf)
#pragma unroll
            for (int nh = 0; nh < 4; ++nh) {
                int r = wm * 32 + mf * 16 + gid;
                int c = wn * 32 + nh * 8 + 2 * tig;
                *(float2*)&Ob[(size_t)r * HH + c] =
                    make_float2(O[mf][nh][0], O[mf][nh][1]);
                *(float2*)&Ob[(size_t)(r + 8) * HH + c] =
                    make_float2(O[mf][nh][2], O[mf][nh][3]);
            }
    } else {
        for (int i = tid; i < 64 * HH; i += 128) Ob[i] = 0.f;
    }
}

// ---------------------------------------------------------------------------
// K6: final reduce of the 4 s-split partials (float4 vectorized)
// ---------------------------------------------------------------------------
__global__ void __launch_bounds__(256) oreduce(float* __restrict__ out)
{
    int i = blockIdx.x * 256 + threadIdx.x;    // float4 index < BB*TT*HH/4
    float4 a = ((const float4*)g_O4[0])[i];
    float4 c = ((const float4*)g_O4[1])[i];
    float4 d = ((const float4*)g_O4[2])[i];
    float4 e = ((const float4*)g_O4[3])[i];
    ((float4*)out)[i] = make_float4(a.x + c.x + d.x + e.x,
                                    a.y + c.y + d.y + e.y,
                                    a.z + c.z + d.z + e.z,
                                    a.w + c.w + d.w + e.w);
}

// ---------------------------------------------------------------------------
// Launch
// ---------------------------------------------------------------------------
extern "C" void kernel_launch(void* const* d_in, const int* in_sizes, int n_in,
                              void* d_out, int out_size)
{
    (void)in_sizes; (void)n_in; (void)out_size;
    const float* idx = (const float*)d_in[0];
    const float* Wk  = (const float*)d_in[1];
    const float* Wq  = (const float*)d_in[2];
    const float* Wv  = (const float*)d_in[3];
    float* out = (float*)d_out;

    cudaFuncSetAttribute(proj_mma,     cudaFuncAttributeMaxDynamicSharedMemorySize, 114688);
    cudaFuncSetAttribute(pass1_colsum, cudaFuncAttributeMaxDynamicSharedMemorySize, 49664);
    cudaFuncSetAttribute(pass2_pv,     cudaFuncAttributeMaxDynamicSharedMemorySize, 32768);

    prep_w<<<768, 256>>>(Wk, Wq, Wv);
    proj_mma<<<256, 256, 114688>>>(idx);
    pass1_colsum<<<dim3(32, 4, BB), 128, 49664>>>();
    vscale<<<(BB * TT * HH / 2) / 256, 256>>>();
    pass2_pv<<<dim3(32, 4, BB), 128, 32768>>>();
    oreduce<<<(BB * TT * HH / 4) / 256, 256>>>(out);
}